// round 11
// baseline (speedup 1.0000x reference)
#include <cuda_runtime.h>
#include <cuda_bf16.h>
#include <cstdint>

#define N_NODES 50000
#define NE      600000
#define D       128
#define SCAN_B  512
#define NSCANB  ((N_NODES + SCAN_B - 1) / SCAN_B)   // 98
#define CNT_BLK ((NE + 255) / 256)                   // 2344

// ---------------------------------------------------------------------------
// Scratch (static device globals — no allocations allowed)
// ---------------------------------------------------------------------------
__device__ int   g_deg[N_NODES];
__device__ float g_dinv[N_NODES];
__device__ float g_msg[(size_t)N_NODES * D];   // h[i] = x[i] @ W  (no dinv)
__device__ int   g_rowptr[N_NODES + 1];
__device__ int   g_cursor[N_NODES];
__device__ int   g_srcidx[NE];
__device__ int   g_blocksum[128];
// x converted to packed bf16 hi/lo: [N][32] uint2 (12.8MB each, L2-resident)
__device__ uint2 g_xhi[(size_t)N_NODES * 32];
__device__ uint2 g_xlo[(size_t)N_NODES * 32];
// W in mma.sync B-fragment layout: [kstep 8][ntile 16][lane 32] uint2, hi & lo
__device__ uint2 g_Bhi[8 * 16 * 32];
__device__ uint2 g_Blo[8 * 16 * 32];

// ---------------------------------------------------------------------------
// bf16 helpers
// ---------------------------------------------------------------------------
__device__ __forceinline__ uint32_t bfpack(float a, float b) {
    __nv_bfloat162 h = __floats2bfloat162_rn(a, b);
    return *(uint32_t*)&h;
}
__device__ __forceinline__ uint32_t bfhi_lo(float a, float b, float& ra, float& rb) {
    __nv_bfloat162 h = __floats2bfloat162_rn(a, b);
    ra = a - __bfloat162float(h.x);
    rb = b - __bfloat162float(h.y);
    return *(uint32_t*)&h;
}

#define MMA16816(c, a0, a1, a2, a3, b0, b1)                                    \
    asm volatile(                                                              \
        "mma.sync.aligned.m16n8k16.row.col.f32.bf16.bf16.f32 "                 \
        "{%0,%1,%2,%3}, {%4,%5,%6,%7}, {%8,%9}, {%0,%1,%2,%3};"                \
        : "+f"((c)[0]), "+f"((c)[1]), "+f"((c)[2]), "+f"((c)[3])               \
        : "r"(a0), "r"(a1), "r"(a2), "r"(a3), "r"(b0), "r"(b1))

// ---------------------------------------------------------------------------
// L1: zero degree
// ---------------------------------------------------------------------------
__global__ void k_init_deg() {
    int i = blockIdx.x * blockDim.x + threadIdx.x;
    if (i < N_NODES) g_deg[i] = 0;
}

// ---------------------------------------------------------------------------
// L2 (fused): blocks [0, CNT_BLK) count in-degree; block CNT_BLK preps W frags
// ---------------------------------------------------------------------------
__global__ __launch_bounds__(256) void k_count_prep(const int* __restrict__ ei,
                                                    const float* __restrict__ W) {
    if (blockIdx.x < CNT_BLK) {
        int e = blockIdx.x * 256 + threadIdx.x;
        if (e < NE) atomicAdd(&g_deg[ei[NE + e]], 1);
        return;
    }
    for (int slot = threadIdx.x; slot < 8 * 16 * 32; slot += 256) {
        int l = slot & 31;
        int j = (slot >> 5) & 15;
        int s = slot >> 9;
        int g = l >> 2, t = l & 3;
        int n  = 8 * j + g;
        int k0 = 16 * s + 2 * t;
        float w00 = W[(k0 + 0) * D + n];
        float w01 = W[(k0 + 1) * D + n];
        float w10 = W[(k0 + 8) * D + n];
        float w11 = W[(k0 + 9) * D + n];
        float r00, r01, r10, r11;
        uint2 hi, lo;
        hi.x = bfhi_lo(w00, w01, r00, r01);
        hi.y = bfhi_lo(w10, w11, r10, r11);
        lo.x = bfpack(r00, r01);
        lo.y = bfpack(r10, r11);
        g_Bhi[slot] = hi;
        g_Blo[slot] = lo;
    }
}

// ---------------------------------------------------------------------------
// L3: streaming convert x -> packed bf16 hi/lo (DRAM-bandwidth-bound)
// One thread per float4; massive TLP saturates HBM read.
// ---------------------------------------------------------------------------
__global__ __launch_bounds__(256) void k_convert(const float* __restrict__ x) {
    int idx = blockIdx.x * 256 + threadIdx.x;      // over N*32 float4
    if (idx >= N_NODES * 32) return;
    float4 v = __ldcs(((const float4*)x) + idx);
    float rx, ry, rz, rw;
    uint2 h, l;
    h.x = bfhi_lo(v.x, v.y, rx, ry);
    h.y = bfhi_lo(v.z, v.w, rz, rw);
    l.x = bfpack(rx, ry);
    l.y = bfpack(rz, rw);
    g_xhi[idx] = h;
    g_xlo[idx] = l;
}

// ---------------------------------------------------------------------------
// L4: GEMM via mma.sync bf16x3: h[i] = x[i] @ W  (reads L2-resident g_xhi/lo)
// 128 threads / 4 warps, 64 rows per block. Warp w: rows 16w..16w+15.
// ---------------------------------------------------------------------------
#define HS 68   // uint32 row stride: 68 mod 32 = 4 -> lanes hit banks 4g+t
__global__ __launch_bounds__(128) void k_gemm_mma() {
    __shared__ uint32_t sHi[64 * HS];   // 17.4 KB packed bf16x2 hi
    __shared__ uint32_t sLo[64 * HS];   // 17.4 KB packed bf16x2 lo

    const int tid = threadIdx.x;
    const int w   = tid >> 5;
    const int l   = tid & 31;
    const int g   = l >> 2, t = l & 3;
    const int base = blockIdx.x * 64;

    // stage hi/lo tiles: 16 front-batched uint4 loads (L2 hits), then STS
    {
        const uint4* Hi4 = (const uint4*)g_xhi + (size_t)base * 16;  // 16 uint4/row
        const uint4* Lo4 = (const uint4*)g_xlo + (size_t)base * 16;
        uint4 vh[8], vl[8];
#pragma unroll
        for (int i = 0; i < 8; i++) {
            int o = tid + 128 * i;       // 1024 uint4 per buffer
            vh[i] = Hi4[o];
            vl[i] = Lo4[o];
        }
#pragma unroll
        for (int i = 0; i < 8; i++) {
            int o = tid + 128 * i;
            int r = o >> 4, cc = o & 15;
            *(uint4*)&sHi[r * HS + 4 * cc] = vh[i];
            *(uint4*)&sLo[r * HS + 4 * cc] = vl[i];
        }
    }
    __syncthreads();

    float c[16][4];
#pragma unroll
    for (int j = 0; j < 16; j++)
#pragma unroll
        for (int q = 0; q < 4; q++) c[j][q] = 0.f;

    const int r0 = 16 * w + g;
    const uint32_t* Ah  = sHi + r0 * HS;
    const uint32_t* Ah8 = Ah + 8 * HS;
    const uint32_t* Al  = sLo + r0 * HS;
    const uint32_t* Al8 = Al + 8 * HS;

#pragma unroll
    for (int s = 0; s < 8; s++) {
        int kp = 8 * s + t;
        uint32_t ah0 = Ah [kp];
        uint32_t ah1 = Ah8[kp];
        uint32_t ah2 = Ah [kp + 4];
        uint32_t ah3 = Ah8[kp + 4];
        uint32_t al0 = Al [kp];
        uint32_t al1 = Al8[kp];
        uint32_t al2 = Al [kp + 4];
        uint32_t al3 = Al8[kp + 4];

        const uint2* bh = g_Bhi + (s * 16) * 32 + l;
        const uint2* bl = g_Blo + (s * 16) * 32 + l;
        // pass 1: hi*hi + lo*hi (shares B-hi fragment)
#pragma unroll
        for (int j = 0; j < 16; j++) {
            uint2 B = bh[j * 32];
            MMA16816(c[j], ah0, ah1, ah2, ah3, B.x, B.y);
            MMA16816(c[j], al0, al1, al2, al3, B.x, B.y);
        }
        // pass 2: hi*lo
#pragma unroll
        for (int j = 0; j < 16; j++) {
            uint2 B = bl[j * 32];
            MMA16816(c[j], ah0, ah1, ah2, ah3, B.x, B.y);
        }
    }

    int R0 = base + r0;
    int R1 = R0 + 8;
#pragma unroll
    for (int j = 0; j < 16; j++) {
        int col = 8 * j + 2 * t;
        if (R0 < N_NODES)
            *(float2*)(g_msg + (size_t)R0 * D + col) = make_float2(c[j][0], c[j][1]);
        if (R1 < N_NODES)
            *(float2*)(g_msg + (size_t)R1 * D + col) = make_float2(c[j][2], c[j][3]);
    }
}

// ---------------------------------------------------------------------------
// L5: block-level exclusive scan of g_deg (+ fused dinv)
// ---------------------------------------------------------------------------
__global__ __launch_bounds__(SCAN_B) void k_scan_block() {
    __shared__ int s[SCAN_B];
    int gid = blockIdx.x * SCAN_B + threadIdx.x;
    int v = (gid < N_NODES) ? g_deg[gid] : 0;
    if (gid < N_NODES) g_dinv[gid] = rsqrtf((float)(v + 1));   // fused
    s[threadIdx.x] = v;
    __syncthreads();
#pragma unroll
    for (int off = 1; off < SCAN_B; off <<= 1) {
        int t = (threadIdx.x >= off) ? s[threadIdx.x - off] : 0;
        __syncthreads();
        s[threadIdx.x] += t;
        __syncthreads();
    }
    if (gid < N_NODES) g_rowptr[gid] = s[threadIdx.x] - v;
    if (threadIdx.x == SCAN_B - 1) g_blocksum[blockIdx.x] = s[SCAN_B - 1];
}

// ---------------------------------------------------------------------------
// L6 (fused top+fix): add cross-block offsets, init cursor
// ---------------------------------------------------------------------------
__global__ __launch_bounds__(256) void k_scan_fix() {
    __shared__ int ss[128];
    int tid = threadIdx.x;
    int gid = blockIdx.x * 256 + tid;
    if (tid < 128) ss[tid] = (tid < NSCANB) ? g_blocksum[tid] : 0;
    __syncthreads();
    if (gid < N_NODES) {
        int blk = gid / SCAN_B;
        int off = 0;
        for (int i = 0; i < blk; i++) off += ss[i];
        int rp = g_rowptr[gid] + off;
        g_rowptr[gid] = rp;
        g_cursor[gid] = rp;
    }
    if (gid == 0) g_rowptr[N_NODES] = NE;
}

// L7: CSR fill
__global__ __launch_bounds__(256) void k_fill(const int* __restrict__ ei) {
    int e = blockIdx.x * blockDim.x + threadIdx.x;
    if (e >= NE) return;
    int pos = atomicAdd(&g_cursor[ei[NE + e]], 1);
    g_srcidx[pos] = ei[e];
}

// ---------------------------------------------------------------------------
// L8: Gather — one warp per destination node, 4-way unroll, .cg loads.
// out[i] = dinv[i] * (sum_p dinv[src_p]*h[src_p] + dinv[i]*h[i]) + b
// ---------------------------------------------------------------------------
__global__ __launch_bounds__(256) void k_gather(float* __restrict__ out,
                                                const float* __restrict__ b) {
    int w    = (blockIdx.x * 256 + threadIdx.x) >> 5;
    int lane = threadIdx.x & 31;
    if (w >= N_NODES) return;

    const float4* gm = (const float4*)g_msg;
    float dv = g_dinv[w];
    float4 self = __ldcg(gm + (size_t)w * 32 + lane);
    float4 acc;
    acc.x = self.x * dv; acc.y = self.y * dv;
    acc.z = self.z * dv; acc.w = self.w * dv;

    int p  = g_rowptr[w];
    int pe = g_rowptr[w + 1];

    for (; p + 3 < pe; p += 4) {
        int s0 = g_srcidx[p];
        int s1 = g_srcidx[p + 1];
        int s2 = g_srcidx[p + 2];
        int s3 = g_srcidx[p + 3];
        float d0 = __ldg(&g_dinv[s0]);
        float d1 = __ldg(&g_dinv[s1]);
        float d2 = __ldg(&g_dinv[s2]);
        float d3 = __ldg(&g_dinv[s3]);
        float4 a0 = __ldcg(gm + (size_t)s0 * 32 + lane);
        float4 a1 = __ldcg(gm + (size_t)s1 * 32 + lane);
        float4 a2 = __ldcg(gm + (size_t)s2 * 32 + lane);
        float4 a3 = __ldcg(gm + (size_t)s3 * 32 + lane);
        acc.x += a0.x * d0 + a1.x * d1 + a2.x * d2 + a3.x * d3;
        acc.y += a0.y * d0 + a1.y * d1 + a2.y * d2 + a3.y * d3;
        acc.z += a0.z * d0 + a1.z * d1 + a2.z * d2 + a3.z * d3;
        acc.w += a0.w * d0 + a1.w * d1 + a2.w * d2 + a3.w * d3;
    }
    for (; p < pe; p++) {
        int s0 = g_srcidx[p];
        float d0 = __ldg(&g_dinv[s0]);
        float4 a = __ldcg(gm + (size_t)s0 * 32 + lane);
        acc.x += a.x * d0; acc.y += a.y * d0;
        acc.z += a.z * d0; acc.w += a.w * d0;
    }

    float4 bb = ((const float4*)b)[lane];
    float4 o;
    o.x = acc.x * dv + bb.x;
    o.y = acc.y * dv + bb.y;
    o.z = acc.z * dv + bb.z;
    o.w = acc.w * dv + bb.w;
    ((float4*)out)[(size_t)w * 32 + lane] = o;
}

// ---------------------------------------------------------------------------
extern "C" void kernel_launch(void* const* d_in, const int* in_sizes, int n_in,
                              void* d_out, int out_size) {
    const float* x   = (const float*)d_in[0];
    const int*   ei  = (const int*)d_in[1];    // int32 (JAX x64-disabled)
    const float* W   = (const float*)d_in[2];
    const float* b   = (const float*)d_in[3];
    float*       out = (float*)d_out;

    k_init_deg<<<(N_NODES + 255) / 256, 256>>>();                 // 1
    k_count_prep<<<CNT_BLK + 1, 256>>>(ei, W);                    // 2
    k_convert<<<(N_NODES * 32 + 255) / 256, 256>>>(x);            // 3
    k_gemm_mma<<<(N_NODES + 63) / 64, 128>>>();                   // 4 <- profiled
    k_scan_block<<<NSCANB, SCAN_B>>>();                           // 5
    k_scan_fix<<<(N_NODES + 255) / 256, 256>>>();                 // 6
    k_fill<<<(NE + 255) / 256, 256>>>(ei);                        // 7
    k_gather<<<(N_NODES * 32 + 255) / 256, 256>>>(out, b);        // 8
}

// round 12
// speedup vs baseline: 1.1436x; 1.1436x over previous
#include <cuda_runtime.h>
#include <cuda_bf16.h>
#include <cstdint>

#define N_NODES 50000
#define NE      600000
#define D       128
#define SCAN_B  512
#define NSCANB  ((N_NODES + SCAN_B - 1) / SCAN_B)   // 98
#define CNT_BLK ((NE + 255) / 256)                   // 2344

// ---------------------------------------------------------------------------
// Scratch (static device globals — no allocations allowed)
// ---------------------------------------------------------------------------
__device__ int   g_deg[N_NODES];
__device__ float g_dinv[N_NODES];
__device__ float g_msg[(size_t)N_NODES * D];   // g[i] = dinv[i] * (x[i] @ W)
__device__ int   g_rowptr[N_NODES + 1];
__device__ int   g_cursor[N_NODES];
__device__ int   g_srcidx[NE];
__device__ int   g_blocksum[128];
// W in mma.sync B-fragment layout: [kstep 8][ntile 16][lane 32] uint2, hi & lo
__device__ uint2 g_Bhi[8 * 16 * 32];
__device__ uint2 g_Blo[8 * 16 * 32];

// ---------------------------------------------------------------------------
// bf16 helpers
// ---------------------------------------------------------------------------
__device__ __forceinline__ uint32_t bfpack(float a, float b) {
    __nv_bfloat162 h = __floats2bfloat162_rn(a, b);
    return *(uint32_t*)&h;
}
__device__ __forceinline__ uint32_t bfhi_lo(float a, float b, float& ra, float& rb) {
    __nv_bfloat162 h = __floats2bfloat162_rn(a, b);
    ra = a - __bfloat162float(h.x);
    rb = b - __bfloat162float(h.y);
    return *(uint32_t*)&h;
}

#define MMA16816(c, a0, a1, a2, a3, b0, b1)                                    \
    asm volatile(                                                              \
        "mma.sync.aligned.m16n8k16.row.col.f32.bf16.bf16.f32 "                 \
        "{%0,%1,%2,%3}, {%4,%5,%6,%7}, {%8,%9}, {%0,%1,%2,%3};"                \
        : "+f"((c)[0]), "+f"((c)[1]), "+f"((c)[2]), "+f"((c)[3])               \
        : "r"(a0), "r"(a1), "r"(a2), "r"(a3), "r"(b0), "r"(b1))

// ---------------------------------------------------------------------------
// L1: zero degree
// ---------------------------------------------------------------------------
__global__ void k_init_deg() {
    int i = blockIdx.x * blockDim.x + threadIdx.x;
    if (i < N_NODES) g_deg[i] = 0;
}

// ---------------------------------------------------------------------------
// L2 (fused): blocks [0, CNT_BLK) count in-degree; block CNT_BLK preps W frags
// ---------------------------------------------------------------------------
__global__ __launch_bounds__(256) void k_count_prep(const int* __restrict__ ei,
                                                    const float* __restrict__ W) {
    if (blockIdx.x < CNT_BLK) {
        int e = blockIdx.x * 256 + threadIdx.x;
        if (e < NE) atomicAdd(&g_deg[ei[NE + e]], 1);
        return;
    }
    for (int slot = threadIdx.x; slot < 8 * 16 * 32; slot += 256) {
        int l = slot & 31;
        int j = (slot >> 5) & 15;
        int s = slot >> 9;
        int g = l >> 2, t = l & 3;
        int n  = 8 * j + g;
        int k0 = 16 * s + 2 * t;
        float w00 = W[(k0 + 0) * D + n];
        float w01 = W[(k0 + 1) * D + n];
        float w10 = W[(k0 + 8) * D + n];
        float w11 = W[(k0 + 9) * D + n];
        float r00, r01, r10, r11;
        uint2 hi, lo;
        hi.x = bfhi_lo(w00, w01, r00, r01);
        hi.y = bfhi_lo(w10, w11, r10, r11);
        lo.x = bfpack(r00, r01);
        lo.y = bfpack(r10, r11);
        g_Bhi[slot] = hi;
        g_Blo[slot] = lo;
    }
}

// ---------------------------------------------------------------------------
// L3: block-level exclusive scan of g_deg (+ fused dinv)
// ---------------------------------------------------------------------------
__global__ __launch_bounds__(SCAN_B) void k_scan_block() {
    __shared__ int s[SCAN_B];
    int gid = blockIdx.x * SCAN_B + threadIdx.x;
    int v = (gid < N_NODES) ? g_deg[gid] : 0;
    if (gid < N_NODES) g_dinv[gid] = rsqrtf((float)(v + 1));   // fused
    s[threadIdx.x] = v;
    __syncthreads();
#pragma unroll
    for (int off = 1; off < SCAN_B; off <<= 1) {
        int t = (threadIdx.x >= off) ? s[threadIdx.x - off] : 0;
        __syncthreads();
        s[threadIdx.x] += t;
        __syncthreads();
    }
    if (gid < N_NODES) g_rowptr[gid] = s[threadIdx.x] - v;
    if (threadIdx.x == SCAN_B - 1) g_blocksum[blockIdx.x] = s[SCAN_B - 1];
}

// ---------------------------------------------------------------------------
// L4: GEMM via mma.sync bf16x3, N-SPLIT: each block does 64 rows x 64 cols.
// blockIdx: rblk = bx >> 1, nh = bx & 1. 128 threads / 4 warps.
// Warp w: rows 16w..16w+15, cols [64*nh, 64*nh+64). 32 accum regs/thread.
// ---------------------------------------------------------------------------
#define HS 68   // uint32 row stride: 68 mod 32 = 4 -> lanes hit banks 4g+t
__global__ __launch_bounds__(128, 6) void k_gemm_mma(const float* __restrict__ x) {
    __shared__ uint32_t sHi[64 * HS];   // 17.4 KB packed bf16x2 hi
    __shared__ uint32_t sLo[64 * HS];   // 17.4 KB packed bf16x2 lo

    const int tid = threadIdx.x;
    const int w   = tid >> 5;
    const int l   = tid & 31;
    const int g   = l >> 2, t = l & 3;
    const int rblk = blockIdx.x >> 1;
    const int nh   = blockIdx.x & 1;
    const int base = rblk * 64;

    // stage + convert x rows -> packed bf16 hi/lo
    for (int i = tid; i < 64 * 32; i += 128) {      // 32 float4 per row
        int r  = i >> 5;
        int c4 = i & 31;
        float4 v = make_float4(0.f, 0.f, 0.f, 0.f);
        if (base + r < N_NODES)
            v = ((const float4*)(x + (size_t)(base + r) * D))[c4];
        float rx, ry, rz, rw;
        uint32_t h0 = bfhi_lo(v.x, v.y, rx, ry);
        uint32_t h1 = bfhi_lo(v.z, v.w, rz, rw);
        uint32_t l0 = bfpack(rx, ry);
        uint32_t l1 = bfpack(rz, rw);
        int o = r * HS + c4 * 2;
        sHi[o] = h0; sHi[o + 1] = h1;
        sLo[o] = l0; sLo[o + 1] = l1;
    }
    __syncthreads();

    float c[8][4];
#pragma unroll
    for (int j = 0; j < 8; j++)
#pragma unroll
        for (int q = 0; q < 4; q++) c[j][q] = 0.f;

    const int r0 = 16 * w + g;
    const uint32_t* Ah  = sHi + r0 * HS;
    const uint32_t* Ah8 = Ah + 8 * HS;
    const uint32_t* Al  = sLo + r0 * HS;
    const uint32_t* Al8 = Al + 8 * HS;

#pragma unroll
    for (int s = 0; s < 8; s++) {
        int kp = 8 * s + t;
        uint32_t ah0 = Ah [kp];
        uint32_t ah1 = Ah8[kp];
        uint32_t ah2 = Ah [kp + 4];
        uint32_t ah3 = Ah8[kp + 4];
        uint32_t al0 = Al [kp];
        uint32_t al1 = Al8[kp];
        uint32_t al2 = Al [kp + 4];
        uint32_t al3 = Al8[kp + 4];

        const uint2* bh = g_Bhi + (s * 16 + nh * 8) * 32 + l;
        const uint2* bl = g_Blo + (s * 16 + nh * 8) * 32 + l;
#pragma unroll
        for (int j = 0; j < 8; j++) {
            uint2 B  = bh[j * 32];
            uint2 Bl = bl[j * 32];
            MMA16816(c[j], ah0, ah1, ah2, ah3, B.x,  B.y);   // hi*hi
            MMA16816(c[j], al0, al1, al2, al3, B.x,  B.y);   // lo*hi
            MMA16816(c[j], ah0, ah1, ah2, ah3, Bl.x, Bl.y);  // hi*lo
        }
    }

    int R0 = base + r0;
    int R1 = R0 + 8;
    float d0 = (R0 < N_NODES) ? g_dinv[R0] : 0.f;
    float d1 = (R1 < N_NODES) ? g_dinv[R1] : 0.f;
#pragma unroll
    for (int j = 0; j < 8; j++) {
        int col = 64 * nh + 8 * j + 2 * t;
        if (R0 < N_NODES)
            *(float2*)(g_msg + (size_t)R0 * D + col) =
                make_float2(c[j][0] * d0, c[j][1] * d0);
        if (R1 < N_NODES)
            *(float2*)(g_msg + (size_t)R1 * D + col) =
                make_float2(c[j][2] * d1, c[j][3] * d1);
    }
}

// ---------------------------------------------------------------------------
// L5 (fused top+fix): add cross-block offsets, init cursor
// ---------------------------------------------------------------------------
__global__ __launch_bounds__(256) void k_scan_fix() {
    __shared__ int ss[128];
    int tid = threadIdx.x;
    int gid = blockIdx.x * 256 + tid;
    if (tid < 128) ss[tid] = (tid < NSCANB) ? g_blocksum[tid] : 0;
    __syncthreads();
    if (gid < N_NODES) {
        int blk = gid / SCAN_B;
        int off = 0;
        for (int i = 0; i < blk; i++) off += ss[i];
        int rp = g_rowptr[gid] + off;
        g_rowptr[gid] = rp;
        g_cursor[gid] = rp;
    }
    if (gid == 0) g_rowptr[N_NODES] = NE;
}

// L6: CSR fill
__global__ __launch_bounds__(256) void k_fill(const int* __restrict__ ei) {
    int e = blockIdx.x * blockDim.x + threadIdx.x;
    if (e >= NE) return;
    int pos = atomicAdd(&g_cursor[ei[NE + e]], 1);
    g_srcidx[pos] = ei[e];
}

// ---------------------------------------------------------------------------
// L7: Gather — one warp per destination node, 4-way unroll, .cg loads
// out[i] = dinv[i] * (sum_{p in CSR(i)} g[src_p] + g[i]) + b
// ---------------------------------------------------------------------------
__global__ __launch_bounds__(256) void k_gather(float* __restrict__ out,
                                                const float* __restrict__ b) {
    int w    = (blockIdx.x * 256 + threadIdx.x) >> 5;
    int lane = threadIdx.x & 31;
    if (w >= N_NODES) return;

    const float4* gm = (const float4*)g_msg;
    float4 acc = __ldcg(gm + (size_t)w * 32 + lane);   // self loop
    int p  = g_rowptr[w];
    int pe = g_rowptr[w + 1];

    for (; p + 3 < pe; p += 4) {
        int s0 = g_srcidx[p];
        int s1 = g_srcidx[p + 1];
        int s2 = g_srcidx[p + 2];
        int s3 = g_srcidx[p + 3];
        float4 a0 = __ldcg(gm + (size_t)s0 * 32 + lane);
        float4 a1 = __ldcg(gm + (size_t)s1 * 32 + lane);
        float4 a2 = __ldcg(gm + (size_t)s2 * 32 + lane);
        float4 a3 = __ldcg(gm + (size_t)s3 * 32 + lane);
        acc.x += (a0.x + a1.x) + (a2.x + a3.x);
        acc.y += (a0.y + a1.y) + (a2.y + a3.y);
        acc.z += (a0.z + a1.z) + (a2.z + a3.z);
        acc.w += (a0.w + a1.w) + (a2.w + a3.w);
    }
    for (; p < pe; p++) {
        int s0 = g_srcidx[p];
        float4 a = __ldcg(gm + (size_t)s0 * 32 + lane);
        acc.x += a.x; acc.y += a.y; acc.z += a.z; acc.w += a.w;
    }

    float dv  = g_dinv[w];
    float4 bb = ((const float4*)b)[lane];
    float4 o;
    o.x = acc.x * dv + bb.x;
    o.y = acc.y * dv + bb.y;
    o.z = acc.z * dv + bb.z;
    o.w = acc.w * dv + bb.w;
    ((float4*)out)[(size_t)w * 32 + lane] = o;
}

// ---------------------------------------------------------------------------
extern "C" void kernel_launch(void* const* d_in, const int* in_sizes, int n_in,
                              void* d_out, int out_size) {
    const float* x   = (const float*)d_in[0];
    const int*   ei  = (const int*)d_in[1];    // int32 (JAX x64-disabled)
    const float* W   = (const float*)d_in[2];
    const float* b   = (const float*)d_in[3];
    float*       out = (float*)d_out;

    k_init_deg<<<(N_NODES + 255) / 256, 256>>>();                 // 1
    k_count_prep<<<CNT_BLK + 1, 256>>>(ei, W);                    // 2
    k_scan_block<<<NSCANB, SCAN_B>>>();                           // 3
    k_gemm_mma<<<2 * ((N_NODES + 63) / 64), 128>>>(x);            // 4 <- profiled
    k_scan_fix<<<(N_NODES + 255) / 256, 256>>>();                 // 5
    k_fill<<<(NE + 255) / 256, 256>>>(ei);                        // 6
    k_gather<<<(N_NODES * 32 + 255) / 256, 256>>>(out, b);        // 7
}

// round 14
// speedup vs baseline: 1.3850x; 1.2111x over previous
#include <cuda_runtime.h>
#include <cuda_bf16.h>
#include <cuda_fp16.h>
#include <cstdint>

#define N_NODES 50000
#define NE      600000
#define D       128
#define SCAN_B  512
#define NSCANB  ((N_NODES + SCAN_B - 1) / SCAN_B)   // 98
#define CNT_BLK ((NE + 255) / 256)                   // 2344

// ---------------------------------------------------------------------------
// Scratch (static device globals — no allocations allowed)
// g_deg starts zero (static init) and is re-zeroed at the end of every call
// by k_gather, so each kernel_launch sees deg == 0 on entry (deterministic).
// ---------------------------------------------------------------------------
__device__ int    g_deg[N_NODES];
__device__ float  g_dinv[N_NODES];
__device__ __half g_msg[(size_t)N_NODES * D];   // fp16: g[i] = dinv[i]*(x[i]@W)
__device__ int    g_rowptr[N_NODES + 1];
__device__ int    g_cursor[N_NODES];
__device__ int    g_srcidx[NE];
__device__ int    g_blocksum[128];
// W in mma.sync B-fragment layout: [kstep 8][ntile 16][lane 32] uint2, hi & lo
__device__ uint2 g_Bhi[8 * 16 * 32];
__device__ uint2 g_Blo[8 * 16 * 32];

// ---------------------------------------------------------------------------
// bf16 helpers
// ---------------------------------------------------------------------------
__device__ __forceinline__ uint32_t bfpack(float a, float b) {
    __nv_bfloat162 h = __floats2bfloat162_rn(a, b);
    return *(uint32_t*)&h;
}
__device__ __forceinline__ uint32_t bfhi_lo(float a, float b, float& ra, float& rb) {
    __nv_bfloat162 h = __floats2bfloat162_rn(a, b);
    ra = a - __bfloat162float(h.x);
    rb = b - __bfloat162float(h.y);
    return *(uint32_t*)&h;
}

#define MMA16816(c, a0, a1, a2, a3, b0, b1)                                    \
    asm volatile(                                                              \
        "mma.sync.aligned.m16n8k16.row.col.f32.bf16.bf16.f32 "                 \
        "{%0,%1,%2,%3}, {%4,%5,%6,%7}, {%8,%9}, {%0,%1,%2,%3};"                \
        : "+f"((c)[0]), "+f"((c)[1]), "+f"((c)[2]), "+f"((c)[3])               \
        : "r"(a0), "r"(a1), "r"(a2), "r"(a3), "r"(b0), "r"(b1))

// ---------------------------------------------------------------------------
// L1 (fused): blocks [0, CNT_BLK) count in-degree; block CNT_BLK preps W frags
// ---------------------------------------------------------------------------
__global__ __launch_bounds__(256) void k_count_prep(const int* __restrict__ ei,
                                                    const float* __restrict__ W) {
    if (blockIdx.x < CNT_BLK) {
        int e = blockIdx.x * 256 + threadIdx.x;
        if (e < NE) atomicAdd(&g_deg[ei[NE + e]], 1);
        return;
    }
    for (int slot = threadIdx.x; slot < 8 * 16 * 32; slot += 256) {
        int l = slot & 31;
        int j = (slot >> 5) & 15;
        int s = slot >> 9;
        int g = l >> 2, t = l & 3;
        int n  = 8 * j + g;
        int k0 = 16 * s + 2 * t;
        float w00 = W[(k0 + 0) * D + n];
        float w01 = W[(k0 + 1) * D + n];
        float w10 = W[(k0 + 8) * D + n];
        float w11 = W[(k0 + 9) * D + n];
        float r00, r01, r10, r11;
        uint2 hi, lo;
        hi.x = bfhi_lo(w00, w01, r00, r01);
        hi.y = bfhi_lo(w10, w11, r10, r11);
        lo.x = bfpack(r00, r01);
        lo.y = bfpack(r10, r11);
        g_Bhi[slot] = hi;
        g_Blo[slot] = lo;
    }
}

// ---------------------------------------------------------------------------
// L2: block-level exclusive scan of g_deg (+ fused dinv)
// ---------------------------------------------------------------------------
__global__ __launch_bounds__(SCAN_B) void k_scan_block() {
    __shared__ int s[SCAN_B];
    int gid = blockIdx.x * SCAN_B + threadIdx.x;
    int v = (gid < N_NODES) ? g_deg[gid] : 0;
    if (gid < N_NODES) g_dinv[gid] = rsqrtf((float)(v + 1));   // fused
    s[threadIdx.x] = v;
    __syncthreads();
#pragma unroll
    for (int off = 1; off < SCAN_B; off <<= 1) {
        int t = (threadIdx.x >= off) ? s[threadIdx.x - off] : 0;
        __syncthreads();
        s[threadIdx.x] += t;
        __syncthreads();
    }
    if (gid < N_NODES) g_rowptr[gid] = s[threadIdx.x] - v;
    if (threadIdx.x == SCAN_B - 1) g_blocksum[blockIdx.x] = s[SCAN_B - 1];
}

// ---------------------------------------------------------------------------
// L3 (fused top+fix): add cross-block offsets, init cursor
// ---------------------------------------------------------------------------
__global__ __launch_bounds__(256) void k_scan_fix() {
    __shared__ int ss[128];
    int tid = threadIdx.x;
    int gid = blockIdx.x * 256 + tid;
    if (tid < 128) ss[tid] = (tid < NSCANB) ? g_blocksum[tid] : 0;
    __syncthreads();
    if (gid < N_NODES) {
        int blk = gid / SCAN_B;
        int off = 0;
        for (int i = 0; i < blk; i++) off += ss[i];
        int rp = g_rowptr[gid] + off;
        g_rowptr[gid] = rp;
        g_cursor[gid] = rp;
    }
    if (gid == 0) g_rowptr[N_NODES] = NE;
}

// ---------------------------------------------------------------------------
// L4: GEMM via mma.sync bf16x3, N-split: 64 rows x 64 cols per block.
// Epilogue stores fp16 messages.
// ---------------------------------------------------------------------------
#define HS 68   // uint32 row stride: 68 mod 32 = 4 -> lanes hit banks 4g+t
__global__ __launch_bounds__(128, 6) void k_gemm_mma(const float* __restrict__ x) {
    __shared__ uint32_t sHi[64 * HS];   // 17.4 KB packed bf16x2 hi
    __shared__ uint32_t sLo[64 * HS];   // 17.4 KB packed bf16x2 lo

    const int tid = threadIdx.x;
    const int w   = tid >> 5;
    const int l   = tid & 31;
    const int g   = l >> 2, t = l & 3;
    const int rblk = blockIdx.x >> 1;
    const int nh   = blockIdx.x & 1;
    const int base = rblk * 64;

    for (int i = tid; i < 64 * 32; i += 128) {      // 32 float4 per row
        int r  = i >> 5;
        int c4 = i & 31;
        float4 v = make_float4(0.f, 0.f, 0.f, 0.f);
        if (base + r < N_NODES)
            v = ((const float4*)(x + (size_t)(base + r) * D))[c4];
        float rx, ry, rz, rw;
        uint32_t h0 = bfhi_lo(v.x, v.y, rx, ry);
        uint32_t h1 = bfhi_lo(v.z, v.w, rz, rw);
        uint32_t l0 = bfpack(rx, ry);
        uint32_t l1 = bfpack(rz, rw);
        int o = r * HS + c4 * 2;
        sHi[o] = h0; sHi[o + 1] = h1;
        sLo[o] = l0; sLo[o + 1] = l1;
    }
    __syncthreads();

    float c[8][4];
#pragma unroll
    for (int j = 0; j < 8; j++)
#pragma unroll
        for (int q = 0; q < 4; q++) c[j][q] = 0.f;

    const int r0 = 16 * w + g;
    const uint32_t* Ah  = sHi + r0 * HS;
    const uint32_t* Ah8 = Ah + 8 * HS;
    const uint32_t* Al  = sLo + r0 * HS;
    const uint32_t* Al8 = Al + 8 * HS;

#pragma unroll
    for (int s = 0; s < 8; s++) {
        int kp = 8 * s + t;
        uint32_t ah0 = Ah [kp];
        uint32_t ah1 = Ah8[kp];
        uint32_t ah2 = Ah [kp + 4];
        uint32_t ah3 = Ah8[kp + 4];
        uint32_t al0 = Al [kp];
        uint32_t al1 = Al8[kp];
        uint32_t al2 = Al [kp + 4];
        uint32_t al3 = Al8[kp + 4];

        const uint2* bh = g_Bhi + (s * 16 + nh * 8) * 32 + l;
        const uint2* bl = g_Blo + (s * 16 + nh * 8) * 32 + l;
#pragma unroll
        for (int j = 0; j < 8; j++) {
            uint2 B  = bh[j * 32];
            uint2 Bl = bl[j * 32];
            MMA16816(c[j], ah0, ah1, ah2, ah3, B.x,  B.y);   // hi*hi
            MMA16816(c[j], al0, al1, al2, al3, B.x,  B.y);   // lo*hi
            MMA16816(c[j], ah0, ah1, ah2, ah3, Bl.x, Bl.y);  // hi*lo
        }
    }

    int R0 = base + r0;
    int R1 = R0 + 8;
    float d0 = (R0 < N_NODES) ? g_dinv[R0] : 0.f;
    float d1 = (R1 < N_NODES) ? g_dinv[R1] : 0.f;
#pragma unroll
    for (int j = 0; j < 8; j++) {
        int col = 64 * nh + 8 * j + 2 * t;
        if (R0 < N_NODES)
            *(__half2*)(g_msg + (size_t)R0 * D + col) =
                __floats2half2_rn(c[j][0] * d0, c[j][1] * d0);
        if (R1 < N_NODES)
            *(__half2*)(g_msg + (size_t)R1 * D + col) =
                __floats2half2_rn(c[j][2] * d1, c[j][3] * d1);
    }
}

// L5: CSR fill
__global__ __launch_bounds__(256) void k_fill(const int* __restrict__ ei) {
    int e = blockIdx.x * blockDim.x + threadIdx.x;
    if (e >= NE) return;
    int pos = atomicAdd(&g_cursor[ei[NE + e]], 1);
    g_srcidx[pos] = ei[e];
}

// ---------------------------------------------------------------------------
// L6: Gather — one warp per destination node, fp16 rows (256B/row), fp32 accum.
// out[i] = dinv[i] * (sum_{p in CSR(i)} g[src_p] + g[i]) + b
// Also re-zeros g_deg for the next call (invariant: deg==0 on entry).
// ---------------------------------------------------------------------------
__device__ __forceinline__ float4 h4_to_f4(uint2 raw) {
    __half2 h0 = *(__half2*)&raw.x;
    __half2 h1 = *(__half2*)&raw.y;
    float2 f0 = __half22float2(h0);
    float2 f1 = __half22float2(h1);
    return make_float4(f0.x, f0.y, f1.x, f1.y);
}

__global__ __launch_bounds__(256) void k_gather(float* __restrict__ out,
                                                const float* __restrict__ b) {
    int w    = (blockIdx.x * 256 + threadIdx.x) >> 5;
    int lane = threadIdx.x & 31;
    if (w >= N_NODES) return;

    const uint2* gm = (const uint2*)g_msg;      // 32 uint2 (= 4 halves) per row
    float4 acc = h4_to_f4(__ldcg(gm + (size_t)w * 32 + lane));   // self loop
    int p  = g_rowptr[w];
    int pe = g_rowptr[w + 1];
    if (lane == 0) g_deg[w] = 0;                // restore invariant for next call

    for (; p + 3 < pe; p += 4) {
        int s0 = g_srcidx[p];
        int s1 = g_srcidx[p + 1];
        int s2 = g_srcidx[p + 2];
        int s3 = g_srcidx[p + 3];
        float4 a0 = h4_to_f4(__ldcg(gm + (size_t)s0 * 32 + lane));
        float4 a1 = h4_to_f4(__ldcg(gm + (size_t)s1 * 32 + lane));
        float4 a2 = h4_to_f4(__ldcg(gm + (size_t)s2 * 32 + lane));
        float4 a3 = h4_to_f4(__ldcg(gm + (size_t)s3 * 32 + lane));
        acc.x += (a0.x + a1.x) + (a2.x + a3.x);
        acc.y += (a0.y + a1.y) + (a2.y + a3.y);
        acc.z += (a0.z + a1.z) + (a2.z + a3.z);
        acc.w += (a0.w + a1.w) + (a2.w + a3.w);
    }
    for (; p < pe; p++) {
        int s0 = g_srcidx[p];
        float4 a = h4_to_f4(__ldcg(gm + (size_t)s0 * 32 + lane));
        acc.x += a.x; acc.y += a.y; acc.z += a.z; acc.w += a.w;
    }

    float dv  = g_dinv[w];
    float4 bb = ((const float4*)b)[lane];
    float4 o;
    o.x = acc.x * dv + bb.x;
    o.y = acc.y * dv + bb.y;
    o.z = acc.z * dv + bb.z;
    o.w = acc.w * dv + bb.w;
    ((float4*)out)[(size_t)w * 32 + lane] = o;
}

// ---------------------------------------------------------------------------
extern "C" void kernel_launch(void* const* d_in, const int* in_sizes, int n_in,
                              void* d_out, int out_size) {
    const float* x   = (const float*)d_in[0];
    const int*   ei  = (const int*)d_in[1];    // int32 (JAX x64-disabled)
    const float* W   = (const float*)d_in[2];
    const float* b   = (const float*)d_in[3];
    float*       out = (float*)d_out;

    k_count_prep<<<CNT_BLK + 1, 256>>>(ei, W);                    // 1
    k_scan_block<<<NSCANB, SCAN_B>>>();                           // 2
    k_scan_fix<<<(N_NODES + 255) / 256, 256>>>();                 // 3
    k_gemm_mma<<<2 * ((N_NODES + 63) / 64), 128>>>(x);            // 4 <- profiled
    k_fill<<<(NE + 255) / 256, 256>>>(ei);                        // 5
    k_gather<<<(N_NODES * 32 + 255) / 256, 256>>>(out, b);        // 6
}